// round 1
// baseline (speedup 1.0000x reference)
#include <cuda_runtime.h>
#include <cstdint>

#define TN        128
#define NTHREADS  256

// ---- shared memory layout (float offsets) ----
// G resident: 32*32*32 = 32768 floats (128KB)
// P0/P1/R: 128 x 33 (padded) each
// scratch: reused — proj phase: Xs[128][68] + Wc[64][33]; out phase: Ut[32][257]
#define OFF_G    0
#define OFF_P0   32768
#define OFF_P1   (OFF_P0 + 128*33)
#define OFF_R    (OFF_P1 + 128*33)
#define OFF_SCR  (OFF_R  + 128*33)
#define OFF_XS   OFF_SCR
#define OFF_WC   (OFF_SCR + 128*68)
#define OFF_UT   OFF_SCR
#define SMEM_FLOATS (OFF_SCR + 128*68 + 64*33)   // 56256 floats
#define SMEM_BYTES  (SMEM_FLOATS * 4)            // 225024 bytes

__global__ __launch_bounds__(NTHREADS, 1)
void hosvd_kernel(const float* __restrict__ X,    // [N][2][256]
                  const float* __restrict__ Gg,   // [32][32][32]
                  const float* __restrict__ Uw,   // [2][32][256]
                  const float* __restrict__ Ub,   // [2][32]
                  const float* __restrict__ Uo,   // [256][32]
                  float* __restrict__ out,        // [N][256]
                  int nNodes)
{
    extern __shared__ float sm[];
    const int tid  = threadIdx.x;
    const int base = blockIdx.x * TN;
    const int ng   = tid >> 3;      // 0..31  (node group: 4 nodes each)
    const int rg   = tid & 7;       // 0..7   (output group: 4 cols each)
    const int ng4  = ng * 4;

    // ---- load G into shared (coalesced float4 copy) ----
    {
        const float4* g4 = reinterpret_cast<const float4*>(Gg);
        float4* s4 = reinterpret_cast<float4*>(sm + OFF_G);
        #pragma unroll
        for (int k = 0; k < 32; k++)
            s4[tid + NTHREADS * k] = g4[tid + NTHREADS * k];
    }

    // ================= Phase 1: projections P[d][n][r] =================
    for (int d = 0; d < 2; d++) {
        float acc[4][4];
        #pragma unroll
        for (int j = 0; j < 4; j++)
            #pragma unroll
            for (int k = 0; k < 4; k++) acc[j][k] = 0.f;

        for (int chunk = 0; chunk < 4; chunk++) {
            const int i0 = chunk * 64;
            __syncthreads();   // protect scratch from previous readers
            // stage X chunk [128 nodes][64 i] -> Xs (row stride 68)
            #pragma unroll
            for (int t = 0; t < 8; t++) {
                int idx = tid + NTHREADS * t;       // 0..2047 float4s
                int n_l = idx >> 4;
                int i4  = (idx & 15) << 2;
                int n   = base + n_l;
                float4 v = make_float4(0.f, 0.f, 0.f, 0.f);
                if (n < nNodes)
                    v = *reinterpret_cast<const float4*>(X + (size_t)n * 512 + d * 256 + i0 + i4);
                *reinterpret_cast<float4*>(sm + OFF_XS + n_l * 68 + i4) = v;
            }
            // stage W chunk transposed: Wc[i][r] (row stride 33)
            #pragma unroll
            for (int t = 0; t < 2; t++) {
                int idx = tid + NTHREADS * t;       // 0..511 float4s
                int r   = idx >> 4;
                int i4  = (idx & 15) << 2;
                float4 v = *reinterpret_cast<const float4*>(Uw + d * 8192 + r * 256 + i0 + i4);
                sm[OFF_WC + (i4 + 0) * 33 + r] = v.x;
                sm[OFF_WC + (i4 + 1) * 33 + r] = v.y;
                sm[OFF_WC + (i4 + 2) * 33 + r] = v.z;
                sm[OFF_WC + (i4 + 3) * 33 + r] = v.w;
            }
            __syncthreads();
            // register-tiled accumulate: 4 nodes x 4 r per thread
            #pragma unroll 4
            for (int ii = 0; ii < 64; ii += 4) {
                float4 xv[4];
                #pragma unroll
                for (int j = 0; j < 4; j++)
                    xv[j] = *reinterpret_cast<const float4*>(sm + OFF_XS + (ng4 + j) * 68 + ii);
                float wv[4][4];
                #pragma unroll
                for (int m = 0; m < 4; m++)
                    #pragma unroll
                    for (int k = 0; k < 4; k++)
                        wv[m][k] = sm[OFF_WC + (ii + m) * 33 + rg * 4 + k];
                #pragma unroll
                for (int j = 0; j < 4; j++)
                    #pragma unroll
                    for (int k = 0; k < 4; k++) {
                        acc[j][k] = fmaf(xv[j].x, wv[0][k], acc[j][k]);
                        acc[j][k] = fmaf(xv[j].y, wv[1][k], acc[j][k]);
                        acc[j][k] = fmaf(xv[j].z, wv[2][k], acc[j][k]);
                        acc[j][k] = fmaf(xv[j].w, wv[3][k], acc[j][k]);
                    }
            }
        }
        // store P with bias (padded stride 33 -> conflict free)
        float* P = sm + (d == 0 ? OFF_P0 : OFF_P1);
        #pragma unroll
        for (int k = 0; k < 4; k++) {
            float b = Ub[d * 32 + rg * 4 + k];
            #pragma unroll
            for (int j = 0; j < 4; j++)
                P[(ng4 + j) * 33 + rg * 4 + k] = acc[j][k] + b;
        }
    }
    __syncthreads();   // P0/P1 visible; scratch free

    // ---- stage transposed U_out into scratch: Ut[c][o] (row stride 257) ----
    #pragma unroll
    for (int t = 0; t < 8; t++) {
        int idx = tid + NTHREADS * t;       // 0..2047 float4s over c
        int o   = idx >> 3;
        int c0  = (idx & 7) << 2;
        float4 v = *reinterpret_cast<const float4*>(Uo + o * 32 + c0);
        sm[OFF_UT + (c0 + 0) * 257 + o] = v.x;
        sm[OFF_UT + (c0 + 1) * 257 + o] = v.y;
        sm[OFF_UT + (c0 + 2) * 257 + o] = v.z;
        sm[OFF_UT + (c0 + 3) * 257 + o] = v.w;
    }

    // ================= Phase 2: Tucker core  r[n,c] = G[a,b,c] p0[n,a] p1[n,b] =================
    {
        float acc[4][4];
        #pragma unroll
        for (int j = 0; j < 4; j++)
            #pragma unroll
            for (int k = 0; k < 4; k++) acc[j][k] = 0.f;

        const float* P0 = sm + OFF_P0;
        const float* P1 = sm + OFF_P1;
        const int cg4 = rg * 4;
        for (int a = 0; a < 32; a++) {
            float p0v[4];
            #pragma unroll
            for (int j = 0; j < 4; j++) p0v[j] = P0[(ng4 + j) * 33 + a];
            const float* gA = sm + OFF_G + a * 1024 + cg4;
            #pragma unroll 4
            for (int b = 0; b < 32; b++) {
                float4 g = *reinterpret_cast<const float4*>(gA + b * 32);
                #pragma unroll
                for (int j = 0; j < 4; j++) {
                    float z = p0v[j] * P1[(ng4 + j) * 33 + b];
                    acc[j][0] = fmaf(z, g.x, acc[j][0]);
                    acc[j][1] = fmaf(z, g.y, acc[j][1]);
                    acc[j][2] = fmaf(z, g.z, acc[j][2]);
                    acc[j][3] = fmaf(z, g.w, acc[j][3]);
                }
            }
        }
        #pragma unroll
        for (int j = 0; j < 4; j++)
            #pragma unroll
            for (int k = 0; k < 4; k++)
                sm[OFF_R + (ng4 + j) * 33 + cg4 + k] = acc[j][k];
    }
    __syncthreads();   // R visible; Ut staged

    // ================= Phase 3: output  out[n,o] = r[n,c] * Uo[o,c] =================
    {
        const int og4 = rg * 4;
        for (int half = 0; half < 2; half++) {
            float4 acc4[4][4];
            #pragma unroll
            for (int j = 0; j < 4; j++)
                #pragma unroll
                for (int k = 0; k < 4; k++)
                    acc4[j][k] = make_float4(0.f, 0.f, 0.f, 0.f);

            #pragma unroll 4
            for (int c = 0; c < 32; c++) {
                float rv[4];
                #pragma unroll
                for (int j = 0; j < 4; j++) rv[j] = sm[OFF_R + (ng4 + j) * 33 + c];
                const float* u = sm + OFF_UT + c * 257 + half * 128 + og4;
                #pragma unroll
                for (int k = 0; k < 4; k++) {
                    float u0 = u[k * 32 + 0];
                    float u1 = u[k * 32 + 1];
                    float u2 = u[k * 32 + 2];
                    float u3 = u[k * 32 + 3];
                    #pragma unroll
                    for (int j = 0; j < 4; j++) {
                        acc4[j][k].x = fmaf(rv[j], u0, acc4[j][k].x);
                        acc4[j][k].y = fmaf(rv[j], u1, acc4[j][k].y);
                        acc4[j][k].z = fmaf(rv[j], u2, acc4[j][k].z);
                        acc4[j][k].w = fmaf(rv[j], u3, acc4[j][k].w);
                    }
                }
            }
            #pragma unroll
            for (int j = 0; j < 4; j++) {
                int n = base + ng4 + j;
                if (n < nNodes) {
                    float* op = out + (size_t)n * 256 + half * 128 + og4;
                    #pragma unroll
                    for (int k = 0; k < 4; k++)
                        *reinterpret_cast<float4*>(op + k * 32) = acc4[j][k];
                }
            }
        }
    }
}

extern "C" void kernel_launch(void* const* d_in, const int* in_sizes, int n_in,
                              void* d_out, int out_size)
{
    const float* X  = (const float*)d_in[0];   // neighbour_states [N,2,256]
    const float* Gg = (const float*)d_in[1];   // G [32,32,32]
    const float* Uw = (const float*)d_in[2];   // U_w [2,32,256]
    const float* Ub = (const float*)d_in[3];   // U_b [2,32]
    const float* Uo = (const float*)d_in[4];   // U_out [256,32]
    float* outp = (float*)d_out;

    int nNodes = in_sizes[0] / 512;            // 2*256 floats per node

    cudaFuncSetAttribute(hosvd_kernel,
                         cudaFuncAttributeMaxDynamicSharedMemorySize, SMEM_BYTES);

    int grid = (nNodes + TN - 1) / TN;
    hosvd_kernel<<<grid, NTHREADS, SMEM_BYTES>>>(X, Gg, Uw, Ub, Uo, outp, nNodes);
}